// round 5
// baseline (speedup 1.0000x reference)
#include <cuda_runtime.h>
#include <cstdint>

#define NN 100000
#define EE 600000

// ---------------- scratch (static device globals; no runtime alloc) ----------
__device__ float g_bufA[NN * 128];
__device__ float g_bufB[NN * 128];
__device__ int   g_cnt[NN];        // zero-initialized at load; re-zeroed by k_fill
__device__ int   g_rowptr[NN + 1];
__device__ int   g_cursor[NN];
__device__ float g_dis[NN];
__device__ int   g_esrc[EE];
__device__ float g_ew[EE];
__device__ int   g_bsum[98];
__device__ int   g_boff[98];

// ---------------- helpers ------------------------------------------------------
__device__ __forceinline__ uint32_t f2tf32(float f) {
    uint32_t u;
    asm("cvt.rna.tf32.f32 %0, %1;" : "=r"(u) : "f"(f));
    return u;
}
__device__ __forceinline__ void mma1688(float* c, const uint32_t* a, const uint32_t* b) {
    asm volatile(
        "mma.sync.aligned.m16n8k8.row.col.f32.tf32.tf32.f32 "
        "{%0,%1,%2,%3}, {%4,%5,%6,%7}, {%8,%9}, {%0,%1,%2,%3};"
        : "+f"(c[0]), "+f"(c[1]), "+f"(c[2]), "+f"(c[3])
        : "r"(a[0]), "r"(a[1]), "r"(a[2]), "r"(a[3]), "r"(b[0]), "r"(b[1]));
}

// ---------------- graph preprocessing ----------------------------------------
__global__ void k_hist(const int* __restrict__ ei) {
    int e = blockIdx.x * blockDim.x + threadIdx.x;
    if (e < EE) atomicAdd(&g_cnt[ei[EE + e]], 1);
}
__global__ void k_scanA() {
    __shared__ int s[1024];
    int t = threadIdx.x;
    int i = blockIdx.x * 1024 + t;
    int v = (i < NN) ? g_cnt[i] : 0;
    s[t] = v;
    __syncthreads();
    for (int o = 512; o > 0; o >>= 1) {
        if (t < o) s[t] += s[t + o];
        __syncthreads();
    }
    if (t == 0) g_bsum[blockIdx.x] = s[0];
}
__global__ void k_scanB() {
    __shared__ int s[128];
    int t = threadIdx.x;
    int v = (t < 98) ? g_bsum[t] : 0;
    s[t] = v;
    __syncthreads();
    for (int o = 1; o < 128; o <<= 1) {
        int u = (t >= o) ? s[t - o] : 0;
        __syncthreads();
        s[t] += u;
        __syncthreads();
    }
    if (t < 98) g_boff[t] = s[t] - v;   // exclusive
    if (t == 97) g_rowptr[NN] = s[97];
}
__global__ void k_scanC() {
    __shared__ int s[1024];
    int t = threadIdx.x;
    int i = blockIdx.x * 1024 + t;
    int v = (i < NN) ? g_cnt[i] : 0;
    s[t] = v;
    __syncthreads();
    for (int o = 1; o < 1024; o <<= 1) {
        int u = (t >= o) ? s[t - o] : 0;
        __syncthreads();
        s[t] += u;
        __syncthreads();
    }
    if (i < NN) {
        int excl = s[t] - v + g_boff[blockIdx.x];
        g_rowptr[i] = excl;
        g_cursor[i] = excl;
        g_dis[i] = rsqrtf((float)(v + 1));
    }
}
// fill CSR; also re-zero g_cnt for the next launch (all readers of g_cnt done).
__global__ void k_fill(const int* __restrict__ ei) {
    int e = blockIdx.x * blockDim.x + threadIdx.x;
    if (e < NN) g_cnt[e] = 0;
    if (e >= EE) return;
    int r = ei[e];
    int c = ei[EE + e];
    int p = atomicAdd(&g_cursor[c], 1);
    g_esrc[p] = r;
    g_ew[p] = g_dis[r] * g_dis[c];
}

// ---------------- layer 1 fused: agg(x) + GEMM 3->128 + bias + relu -----------
// warp per node; edge-parallel gather (lane per edge), shfl reduce, then each
// lane produces 4 output columns.
__global__ void __launch_bounds__(256) k_l1(const float* __restrict__ x,
                                            const float* __restrict__ W1,
                                            const float* __restrict__ b1) {
    __shared__ float ws[384];
    __shared__ float bs[128];
    for (int i = threadIdx.x; i < 384; i += 256) ws[i] = W1[i];
    if (threadIdx.x < 128) bs[threadIdx.x] = b1[threadIdx.x];
    __syncthreads();
    int node = blockIdx.x * 8 + (threadIdx.x >> 5);
    if (node >= NN) return;
    int lane = threadIdx.x & 31;
    float a0 = 0.f, a1 = 0.f, a2 = 0.f;
    int p0 = g_rowptr[node], p1 = g_rowptr[node + 1];
    for (int p = p0 + lane; p < p1; p += 32) {
        int s = g_esrc[p];
        float w = g_ew[p];
        a0 += w * x[s * 3 + 0];
        a1 += w * x[s * 3 + 1];
        a2 += w * x[s * 3 + 2];
    }
#pragma unroll
    for (int o = 16; o > 0; o >>= 1) {
        a0 += __shfl_down_sync(0xFFFFFFFFu, a0, o);
        a1 += __shfl_down_sync(0xFFFFFFFFu, a1, o);
        a2 += __shfl_down_sync(0xFFFFFFFFu, a2, o);
    }
    a0 = __shfl_sync(0xFFFFFFFFu, a0, 0);
    a1 = __shfl_sync(0xFFFFFFFFu, a1, 0);
    a2 = __shfl_sync(0xFFFFFFFFu, a2, 0);
    float d = g_dis[node];
    float inv = d * d;
    a0 += inv * x[node * 3 + 0];
    a1 += inv * x[node * 3 + 1];
    a2 += inv * x[node * 3 + 2];
    int c = lane * 4;
    float4 o;
    o.x = fmaxf(bs[c + 0] + a0 * ws[c + 0] + a1 * ws[128 + c + 0] + a2 * ws[256 + c + 0], 0.f);
    o.y = fmaxf(bs[c + 1] + a0 * ws[c + 1] + a1 * ws[128 + c + 1] + a2 * ws[256 + c + 1], 0.f);
    o.z = fmaxf(bs[c + 2] + a0 * ws[c + 2] + a1 * ws[128 + c + 2] + a2 * ws[256 + c + 2], 0.f);
    o.w = fmaxf(bs[c + 3] + a0 * ws[c + 3] + a1 * ws[128 + c + 3] + a2 * ws[256 + c + 3], 0.f);
    *(float4*)&g_bufA[node * 128 + c] = o;
}

// ---------------- aggregation kernels (gather, atomic-free, MLP=4) ------------
__global__ void k_agg128() {
    int node = blockIdx.x * 8 + (threadIdx.x >> 5);
    if (node >= NN) return;
    int lane = threadIdx.x & 31;
    int off = lane * 4;
    float d = g_dis[node];
    float inv = d * d;
    float4 acc0 = *(const float4*)&g_bufB[node * 128 + off];
    acc0.x *= inv; acc0.y *= inv; acc0.z *= inv; acc0.w *= inv;
    float4 acc1 = make_float4(0.f, 0.f, 0.f, 0.f);
    float4 acc2 = make_float4(0.f, 0.f, 0.f, 0.f);
    float4 acc3 = make_float4(0.f, 0.f, 0.f, 0.f);
    int p = g_rowptr[node], p1 = g_rowptr[node + 1];
    for (; p + 4 <= p1; p += 4) {
        int s0 = g_esrc[p + 0], s1 = g_esrc[p + 1], s2 = g_esrc[p + 2], s3 = g_esrc[p + 3];
        float w0 = g_ew[p + 0], w1 = g_ew[p + 1], w2 = g_ew[p + 2], w3 = g_ew[p + 3];
        float4 v0 = *(const float4*)&g_bufB[s0 * 128 + off];
        float4 v1 = *(const float4*)&g_bufB[s1 * 128 + off];
        float4 v2 = *(const float4*)&g_bufB[s2 * 128 + off];
        float4 v3 = *(const float4*)&g_bufB[s3 * 128 + off];
        acc0.x += w0 * v0.x; acc0.y += w0 * v0.y; acc0.z += w0 * v0.z; acc0.w += w0 * v0.w;
        acc1.x += w1 * v1.x; acc1.y += w1 * v1.y; acc1.z += w1 * v1.z; acc1.w += w1 * v1.w;
        acc2.x += w2 * v2.x; acc2.y += w2 * v2.y; acc2.z += w2 * v2.z; acc2.w += w2 * v2.w;
        acc3.x += w3 * v3.x; acc3.y += w3 * v3.y; acc3.z += w3 * v3.z; acc3.w += w3 * v3.w;
    }
    for (; p < p1; p++) {
        int s = g_esrc[p];
        float w = g_ew[p];
        float4 v = *(const float4*)&g_bufB[s * 128 + off];
        acc0.x += w * v.x; acc0.y += w * v.y; acc0.z += w * v.z; acc0.w += w * v.w;
    }
    acc0.x += acc1.x + acc2.x + acc3.x;
    acc0.y += acc1.y + acc2.y + acc3.y;
    acc0.z += acc1.z + acc2.z + acc3.z;
    acc0.w += acc1.w + acc2.w + acc3.w;
    *(float4*)&g_bufA[node * 128 + off] = acc0;
}
__global__ void k_agg64() {
    int node = blockIdx.x * 8 + (threadIdx.x >> 5);
    if (node >= NN) return;
    int lane = threadIdx.x & 31;
    int off = lane * 2;
    float d = g_dis[node];
    float inv = d * d;
    float2 acc0 = *(const float2*)&g_bufB[node * 64 + off];
    acc0.x *= inv; acc0.y *= inv;
    float2 acc1 = make_float2(0.f, 0.f);
    float2 acc2 = make_float2(0.f, 0.f);
    float2 acc3 = make_float2(0.f, 0.f);
    int p = g_rowptr[node], p1 = g_rowptr[node + 1];
    for (; p + 4 <= p1; p += 4) {
        int s0 = g_esrc[p + 0], s1 = g_esrc[p + 1], s2 = g_esrc[p + 2], s3 = g_esrc[p + 3];
        float w0 = g_ew[p + 0], w1 = g_ew[p + 1], w2 = g_ew[p + 2], w3 = g_ew[p + 3];
        float2 v0 = *(const float2*)&g_bufB[s0 * 64 + off];
        float2 v1 = *(const float2*)&g_bufB[s1 * 64 + off];
        float2 v2 = *(const float2*)&g_bufB[s2 * 64 + off];
        float2 v3 = *(const float2*)&g_bufB[s3 * 64 + off];
        acc0.x += w0 * v0.x; acc0.y += w0 * v0.y;
        acc1.x += w1 * v1.x; acc1.y += w1 * v1.y;
        acc2.x += w2 * v2.x; acc2.y += w2 * v2.y;
        acc3.x += w3 * v3.x; acc3.y += w3 * v3.y;
    }
    for (; p < p1; p++) {
        int s = g_esrc[p];
        float w = g_ew[p];
        float2 v = *(const float2*)&g_bufB[s * 64 + off];
        acc0.x += w * v.x; acc0.y += w * v.y;
    }
    acc0.x += acc1.x + acc2.x + acc3.x;
    acc0.y += acc1.y + acc2.y + acc3.y;
    *(float2*)&g_bufA[node * 64 + off] = acc0;
}
__global__ void k_agg_out(float* __restrict__ out, const float* __restrict__ b5) {
    int i = blockIdx.x * blockDim.x + threadIdx.x;
    if (i >= NN) return;
    float d = g_dis[i];
    float acc0 = g_bufB[i] * d * d + b5[0];
    float acc1 = 0.f, acc2 = 0.f, acc3 = 0.f;
    int p = g_rowptr[i], p1 = g_rowptr[i + 1];
    for (; p + 4 <= p1; p += 4) {
        acc0 += g_ew[p + 0] * g_bufB[g_esrc[p + 0]];
        acc1 += g_ew[p + 1] * g_bufB[g_esrc[p + 1]];
        acc2 += g_ew[p + 2] * g_bufB[g_esrc[p + 2]];
        acc3 += g_ew[p + 3] * g_bufB[g_esrc[p + 3]];
    }
    for (; p < p1; p++) acc0 += g_ew[p] * g_bufB[g_esrc[p]];
    out[i] = acc0 + acc1 + acc2 + acc3;
}

// ---------------- layer 5 (K=64, M=1, SIMT) -----------------------------------
__global__ void k_gemm5(const float* __restrict__ W5, const float* __restrict__ b4) {
    __shared__ float ws[64];
    __shared__ float bs[64];
    if (threadIdx.x < 64) {
        ws[threadIdx.x] = W5[threadIdx.x];
        bs[threadIdx.x] = b4[threadIdx.x];
    }
    __syncthreads();
    int row = blockIdx.x * blockDim.x + threadIdx.x;
    if (row >= NN) return;
    float acc = 0.f;
#pragma unroll
    for (int k = 0; k < 64; k++)
        acc += fmaxf(g_bufA[row * 64 + k] + bs[k], 0.f) * ws[k];
    g_bufB[row] = acc;
}

// ---------------- tf32 mma.sync GEMM (layers 2-4) -----------------------------
// g_bufB[N,M] = f(g_bufA[N,K]) @ W[K,M];  f = relu(v + inb) when IN_T.
// CTA: 128 rows x M cols, 256 threads = 8 warps in 4(m) x 2(n) grid.
template <int K, int M, bool IN_T>
__global__ void __launch_bounds__(256) k_tcgemm(const float* __restrict__ W,
                                                const float* __restrict__ inb) {
    constexpr int LDA = K + 4;
    constexpr int LDB = M + 4;
    constexpr int NT = M / 16;
    extern __shared__ uint32_t sh[];
    uint32_t* As = sh;                  // [128][LDA]
    uint32_t* Bs = sh + 128 * LDA;      // [K][LDB]
    const int tid = threadIdx.x;
    const int rowBase = blockIdx.x * 128;

    constexpr int M4 = M / 4;
#pragma unroll 4
    for (int idx = tid; idx < K * M4; idx += 256) {
        int k = idx / M4;
        int n = (idx % M4) * 4;
        float4 v = *(const float4*)&W[k * M + n];
        uint4 u = make_uint4(f2tf32(v.x), f2tf32(v.y), f2tf32(v.z), f2tf32(v.w));
        *(uint4*)&Bs[k * LDB + n] = u;
    }
    constexpr int K4 = K / 4;
#pragma unroll 4
    for (int idx = tid; idx < 128 * K4; idx += 256) {
        int r = idx / K4;
        int kc = (idx % K4) * 4;
        int gr = rowBase + r;
        float4 v = make_float4(0.f, 0.f, 0.f, 0.f);
        if (gr < NN) v = *(const float4*)&g_bufA[gr * K + kc];
        if (IN_T) {
            v.x = fmaxf(v.x + inb[kc + 0], 0.f);
            v.y = fmaxf(v.y + inb[kc + 1], 0.f);
            v.z = fmaxf(v.z + inb[kc + 2], 0.f);
            v.w = fmaxf(v.w + inb[kc + 3], 0.f);
        }
        uint4 u = make_uint4(f2tf32(v.x), f2tf32(v.y), f2tf32(v.z), f2tf32(v.w));
        *(uint4*)&As[r * LDA + kc] = u;
    }
    __syncthreads();

    const int wid = tid >> 5;
    const int lane = tid & 31;
    const int g = lane >> 2;
    const int tg = lane & 3;
    const int mRow = (wid & 3) * 32;
    const int nCol = (wid >> 2) * (M / 2);

    float acc[2][NT][4];
#pragma unroll
    for (int mt = 0; mt < 2; mt++)
#pragma unroll
        for (int nt = 0; nt < NT; nt++)
#pragma unroll
            for (int i = 0; i < 4; i++) acc[mt][nt][i] = 0.f;

#pragma unroll
    for (int k0 = 0; k0 < K; k0 += 8) {
        uint32_t a[2][4];
#pragma unroll
        for (int mt = 0; mt < 2; mt++) {
            int r = mRow + mt * 16 + g;
            a[mt][0] = As[r * LDA + k0 + tg];
            a[mt][1] = As[(r + 8) * LDA + k0 + tg];
            a[mt][2] = As[r * LDA + k0 + tg + 4];
            a[mt][3] = As[(r + 8) * LDA + k0 + tg + 4];
        }
        uint32_t b[NT][2];
#pragma unroll
        for (int nt = 0; nt < NT; nt++) {
            int c = nCol + nt * 8 + g;
            b[nt][0] = Bs[(k0 + tg) * LDB + c];
            b[nt][1] = Bs[(k0 + tg + 4) * LDB + c];
        }
#pragma unroll
        for (int mt = 0; mt < 2; mt++)
#pragma unroll
            for (int nt = 0; nt < NT; nt++) mma1688(acc[mt][nt], a[mt], b[nt]);
    }

#pragma unroll
    for (int mt = 0; mt < 2; mt++) {
        int r0 = rowBase + mRow + mt * 16 + g;
        int r1 = r0 + 8;
#pragma unroll
        for (int nt = 0; nt < NT; nt++) {
            int c = nCol + nt * 8 + 2 * tg;
            if (r0 < NN)
                *(float2*)&g_bufB[r0 * M + c] = make_float2(acc[mt][nt][0], acc[mt][nt][1]);
            if (r1 < NN)
                *(float2*)&g_bufB[r1 * M + c] = make_float2(acc[mt][nt][2], acc[mt][nt][3]);
        }
    }
}

// ---------------- launcher ----------------------------------------------------
extern "C" void kernel_launch(void* const* d_in, const int* in_sizes, int n_in,
                              void* d_out, int out_size) {
    const float* x  = (const float*)d_in[0];
    const int*   ei = (const int*)d_in[1];
    const float* W1 = (const float*)d_in[2];
    const float* b1 = (const float*)d_in[3];
    const float* W2 = (const float*)d_in[4];
    const float* b2 = (const float*)d_in[5];
    const float* W3 = (const float*)d_in[6];
    const float* b3 = (const float*)d_in[7];
    const float* W4 = (const float*)d_in[8];
    const float* b4 = (const float*)d_in[9];
    const float* W5 = (const float*)d_in[10];
    const float* b5 = (const float*)d_in[11];
    float* out = (float*)d_out;

    constexpr int SM2 = (128 * 132 + 128 * 132) * 4;  // 135168
    constexpr int SM3 = (128 * 132 + 128 * 68) * 4;   // 102400
    constexpr int SM4 = (128 * 68 + 64 * 68) * 4;     // 52224
    cudaFuncSetAttribute(k_tcgemm<128, 128, false>,
                         cudaFuncAttributeMaxDynamicSharedMemorySize, SM2);
    cudaFuncSetAttribute(k_tcgemm<128, 64, true>,
                         cudaFuncAttributeMaxDynamicSharedMemorySize, SM3);
    cudaFuncSetAttribute(k_tcgemm<64, 64, true>,
                         cudaFuncAttributeMaxDynamicSharedMemorySize, SM4);

    const int NB_N = (NN + 255) / 256;
    const int NB_E = (EE + 255) / 256;
    const int NB_W = (NN + 7) / 8;
    const int GB   = (NN + 127) / 128;

    // graph preprocessing: CSR by target + symmetric norms
    k_hist<<<NB_E, 256>>>(ei);
    k_scanA<<<98, 1024>>>();
    k_scanB<<<1, 128>>>();
    k_scanC<<<98, 1024>>>();
    k_fill<<<NB_E, 256>>>(ei);

    // L1 fused: A1 = Agg(x); H1 = relu(A1 @ W1 + b1)
    k_l1<<<NB_W, 256>>>(x, W1, b1);

    // L2: T2 = H1 @ W2 ; A2 = Agg(T2)
    k_tcgemm<128, 128, false><<<GB, 256, SM2>>>(W2, nullptr);
    k_agg128<<<NB_W, 256>>>();

    // L3: T3 = relu(A2 + b2) @ W3 ; A3 = Agg(T3)
    k_tcgemm<128, 64, true><<<GB, 256, SM3>>>(W3, b2);
    k_agg64<<<NB_W, 256>>>();

    // L4: T4 = relu(A3 + b3) @ W4 ; A4 = Agg(T4)
    k_tcgemm<64, 64, true><<<GB, 256, SM4>>>(W4, b3);
    k_agg64<<<NB_W, 256>>>();

    // L5: s = relu(A4 + b4) @ W5 ; out = Agg(s) + b5
    k_gemm5<<<NB_N, 256>>>(W5, b4);
    k_agg_out<<<NB_N, 256>>>(out, b5);
}

// round 6
// speedup vs baseline: 1.0762x; 1.0762x over previous
#include <cuda_runtime.h>
#include <cstdint>

#define NN 100000
#define EE 600000

// ---------------- scratch (static device globals; no runtime alloc) ----------
__device__ float g_bufA[NN * 128];
__device__ float g_bufB[NN * 128];
__device__ float g_ax[NN * 3];
__device__ int   g_cnt[NN];        // zero at load; re-zeroed by k_fill each run
__device__ int   g_rowptr[NN + 1];
__device__ float g_dis[NN];
__device__ int   g_esrc[EE];
__device__ float g_ew[EE];
__device__ int   g_rank[EE];
__device__ int   g_bsum[98];
__device__ unsigned g_barcnt = 0;
__device__ volatile unsigned g_barrel = 0;

// ---------------- helpers ------------------------------------------------------
__device__ __forceinline__ uint32_t f2tf32(float f) {
    uint32_t u;
    asm("cvt.rna.tf32.f32 %0, %1;" : "=r"(u) : "f"(f));
    return u;
}
__device__ __forceinline__ void mma1688(float* c, const uint32_t* a, const uint32_t* b) {
    asm volatile(
        "mma.sync.aligned.m16n8k8.row.col.f32.tf32.tf32.f32 "
        "{%0,%1,%2,%3}, {%4,%5,%6,%7}, {%8,%9}, {%0,%1,%2,%3};"
        : "+f"(c[0]), "+f"(c[1]), "+f"(c[2]), "+f"(c[3])
        : "r"(a[0]), "r"(a[1]), "r"(a[2]), "r"(a[3]), "r"(b[0]), "r"(b[1]));
}

// ---------------- graph preprocessing ----------------------------------------
// hist: count targets AND record each edge's rank within its target bucket.
__global__ void k_hist(const int* __restrict__ ei) {
    int e = blockIdx.x * blockDim.x + threadIdx.x;
    if (e >= EE) return;
    int c = ei[EE + e];
    g_rank[e] = atomicAdd(&g_cnt[c], 1);
}

// fused scan: 98 blocks x 1024 threads, all co-resident (98 < 148 SMs).
// Phase 1: block-local inclusive scan (warp shuffles) + block sums.
// Global spin barrier. Phase 2: block prefix from g_bsum, write rowptr/dis.
__global__ void __launch_bounds__(1024) k_scan() {
    const int t = threadIdx.x;
    const int lane = t & 31;
    const int w = t >> 5;
    const int i = blockIdx.x * 1024 + t;
    int v = (i < NN) ? g_cnt[i] : 0;

    // warp inclusive scan
    int sc = v;
#pragma unroll
    for (int o = 1; o < 32; o <<= 1) {
        int u = __shfl_up_sync(0xFFFFFFFFu, sc, o);
        if (lane >= o) sc += u;
    }
    __shared__ int wsum[32];
    if (lane == 31) wsum[w] = sc;
    __syncthreads();
    if (w == 0) {
        int ws = wsum[lane];
#pragma unroll
        for (int o = 1; o < 32; o <<= 1) {
            int u = __shfl_up_sync(0xFFFFFFFFu, ws, o);
            if (lane >= o) ws += u;
        }
        wsum[lane] = ws;
    }
    __syncthreads();
    int incl = sc + ((w > 0) ? wsum[w - 1] : 0);
    if (t == 0) g_bsum[blockIdx.x] = wsum[31];

    // global barrier (epoch-based; state self-resets for graph replay)
    __threadfence();
    __syncthreads();
    if (t == 0) {
        unsigned epoch = g_barrel;
        if (atomicAdd(&g_barcnt, 1u) == 97u) {
            g_barcnt = 0;
            __threadfence();
            g_barrel = epoch + 1;
        } else {
            while (g_barrel == epoch) {}
        }
    }
    __syncthreads();

    // block prefix: sum of g_bsum[0..blockIdx-1] via tree reduce
    __shared__ int red[128];
    if (t < 128) red[t] = (t < blockIdx.x) ? g_bsum[t] : 0;
    __syncthreads();
#pragma unroll
    for (int o = 64; o > 0; o >>= 1) {
        if (t < o) red[t] += red[t + o];
        __syncthreads();
    }
    int excl = incl - v + red[0];
    if (i < NN) {
        g_rowptr[i] = excl;
        g_dis[i] = rsqrtf((float)(v + 1));
    }
    if (i == NN - 1) g_rowptr[NN] = excl + v;
}

// fill CSR atomic-free via precomputed ranks; re-zero g_cnt for next replay.
__global__ void k_fill(const int* __restrict__ ei) {
    int e = blockIdx.x * blockDim.x + threadIdx.x;
    if (e < NN) g_cnt[e] = 0;
    if (e >= EE) return;
    int r = ei[e];
    int c = ei[EE + e];
    int p = g_rowptr[c] + g_rank[e];
    g_esrc[p] = r;
    g_ew[p] = g_dis[r] * g_dis[c];
}

// ---------------- aggregation kernels (gather, atomic-free) ------------------
__global__ void k_agg0(const float* __restrict__ x) {
    int i = blockIdx.x * blockDim.x + threadIdx.x;
    if (i >= NN) return;
    float d = g_dis[i];
    float inv = d * d;
    float a0 = x[i * 3 + 0] * inv;
    float a1 = x[i * 3 + 1] * inv;
    float a2 = x[i * 3 + 2] * inv;
    int p1 = g_rowptr[i + 1];
    for (int p = g_rowptr[i]; p < p1; p++) {
        int s = g_esrc[p];
        float w = g_ew[p];
        a0 += w * x[s * 3 + 0];
        a1 += w * x[s * 3 + 1];
        a2 += w * x[s * 3 + 2];
    }
    g_ax[i * 3 + 0] = a0;
    g_ax[i * 3 + 1] = a1;
    g_ax[i * 3 + 2] = a2;
}
__global__ void k_agg128() {
    int node = blockIdx.x * 8 + (threadIdx.x >> 5);
    if (node >= NN) return;
    int lane = threadIdx.x & 31;
    int off = lane * 4;
    float d = g_dis[node];
    float inv = d * d;
    float4 acc = *(const float4*)&g_bufB[node * 128 + off];
    acc.x *= inv; acc.y *= inv; acc.z *= inv; acc.w *= inv;
    int p1 = g_rowptr[node + 1];
    for (int p = g_rowptr[node]; p < p1; p++) {
        int s = g_esrc[p];
        float w = g_ew[p];
        float4 v = *(const float4*)&g_bufB[s * 128 + off];
        acc.x += w * v.x; acc.y += w * v.y; acc.z += w * v.z; acc.w += w * v.w;
    }
    *(float4*)&g_bufA[node * 128 + off] = acc;
}
__global__ void k_agg64() {
    int node = blockIdx.x * 8 + (threadIdx.x >> 5);
    if (node >= NN) return;
    int lane = threadIdx.x & 31;
    int off = lane * 2;
    float d = g_dis[node];
    float inv = d * d;
    float2 acc = *(const float2*)&g_bufB[node * 64 + off];
    acc.x *= inv; acc.y *= inv;
    int p1 = g_rowptr[node + 1];
    for (int p = g_rowptr[node]; p < p1; p++) {
        int s = g_esrc[p];
        float w = g_ew[p];
        float2 v = *(const float2*)&g_bufB[s * 64 + off];
        acc.x += w * v.x; acc.y += w * v.y;
    }
    *(float2*)&g_bufA[node * 64 + off] = acc;
}
__global__ void k_agg_out(float* __restrict__ out, const float* __restrict__ b5) {
    int i = blockIdx.x * blockDim.x + threadIdx.x;
    if (i >= NN) return;
    float d = g_dis[i];
    float acc = g_bufB[i] * d * d + b5[0];
    int p1 = g_rowptr[i + 1];
    for (int p = g_rowptr[i]; p < p1; p++)
        acc += g_ew[p] * g_bufB[g_esrc[p]];
    out[i] = acc;
}

// ---------------- small GEMMs (layers 1 and 5, SIMT) --------------------------
__global__ void k_gemm1(const float* __restrict__ W1, const float* __restrict__ b1) {
    __shared__ float ws[3 * 128];
    __shared__ float bs[128];
    for (int i = threadIdx.x; i < 384; i += 256) ws[i] = W1[i];
    if (threadIdx.x < 128) bs[threadIdx.x] = b1[threadIdx.x];
    __syncthreads();
    int gid = blockIdx.x * 256 + threadIdx.x;
    int row = gid >> 5;
    int c = (gid & 31) * 4;
    if (row >= NN) return;
    float a0 = g_ax[row * 3 + 0];
    float a1 = g_ax[row * 3 + 1];
    float a2 = g_ax[row * 3 + 2];
    float4 o;
    o.x = fmaxf(bs[c + 0] + a0 * ws[c + 0] + a1 * ws[128 + c + 0] + a2 * ws[256 + c + 0], 0.f);
    o.y = fmaxf(bs[c + 1] + a0 * ws[c + 1] + a1 * ws[128 + c + 1] + a2 * ws[256 + c + 1], 0.f);
    o.z = fmaxf(bs[c + 2] + a0 * ws[c + 2] + a1 * ws[128 + c + 2] + a2 * ws[256 + c + 2], 0.f);
    o.w = fmaxf(bs[c + 3] + a0 * ws[c + 3] + a1 * ws[128 + c + 3] + a2 * ws[256 + c + 3], 0.f);
    *(float4*)&g_bufA[row * 128 + c] = o;
}
__global__ void k_gemm5(const float* __restrict__ W5, const float* __restrict__ b4) {
    __shared__ float ws[64];
    __shared__ float bs[64];
    if (threadIdx.x < 64) {
        ws[threadIdx.x] = W5[threadIdx.x];
        bs[threadIdx.x] = b4[threadIdx.x];
    }
    __syncthreads();
    int row = blockIdx.x * blockDim.x + threadIdx.x;
    if (row >= NN) return;
    float acc = 0.f;
#pragma unroll
    for (int k = 0; k < 64; k++)
        acc += fmaxf(g_bufA[row * 64 + k] + bs[k], 0.f) * ws[k];
    g_bufB[row] = acc;
}

// ---------------- tf32 mma.sync GEMM (layers 2-4) -----------------------------
template <int K, int M, bool IN_T>
__global__ void __launch_bounds__(256) k_tcgemm(const float* __restrict__ W,
                                                const float* __restrict__ inb) {
    constexpr int LDA = K + 4;
    constexpr int LDB = M + 4;
    constexpr int NT = M / 16;
    extern __shared__ uint32_t sh[];
    uint32_t* As = sh;                  // [128][LDA]
    uint32_t* Bs = sh + 128 * LDA;      // [K][LDB]
    const int tid = threadIdx.x;
    const int rowBase = blockIdx.x * 128;

    constexpr int M4 = M / 4;
#pragma unroll 4
    for (int idx = tid; idx < K * M4; idx += 256) {
        int k = idx / M4;
        int n = (idx % M4) * 4;
        float4 v = *(const float4*)&W[k * M + n];
        uint4 u = make_uint4(f2tf32(v.x), f2tf32(v.y), f2tf32(v.z), f2tf32(v.w));
        *(uint4*)&Bs[k * LDB + n] = u;
    }
    constexpr int K4 = K / 4;
#pragma unroll 4
    for (int idx = tid; idx < 128 * K4; idx += 256) {
        int r = idx / K4;
        int kc = (idx % K4) * 4;
        int gr = rowBase + r;
        float4 v = make_float4(0.f, 0.f, 0.f, 0.f);
        if (gr < NN) v = *(const float4*)&g_bufA[gr * K + kc];
        if (IN_T) {
            v.x = fmaxf(v.x + inb[kc + 0], 0.f);
            v.y = fmaxf(v.y + inb[kc + 1], 0.f);
            v.z = fmaxf(v.z + inb[kc + 2], 0.f);
            v.w = fmaxf(v.w + inb[kc + 3], 0.f);
        }
        uint4 u = make_uint4(f2tf32(v.x), f2tf32(v.y), f2tf32(v.z), f2tf32(v.w));
        *(uint4*)&As[r * LDA + kc] = u;
    }
    __syncthreads();

    const int wid = tid >> 5;
    const int lane = tid & 31;
    const int g = lane >> 2;
    const int tg = lane & 3;
    const int mRow = (wid & 3) * 32;
    const int nCol = (wid >> 2) * (M / 2);

    float acc[2][NT][4];
#pragma unroll
    for (int mt = 0; mt < 2; mt++)
#pragma unroll
        for (int nt = 0; nt < NT; nt++)
#pragma unroll
            for (int i = 0; i < 4; i++) acc[mt][nt][i] = 0.f;

#pragma unroll
    for (int k0 = 0; k0 < K; k0 += 8) {
        uint32_t a[2][4];
#pragma unroll
        for (int mt = 0; mt < 2; mt++) {
            int r = mRow + mt * 16 + g;
            a[mt][0] = As[r * LDA + k0 + tg];
            a[mt][1] = As[(r + 8) * LDA + k0 + tg];
            a[mt][2] = As[r * LDA + k0 + tg + 4];
            a[mt][3] = As[(r + 8) * LDA + k0 + tg + 4];
        }
        uint32_t b[NT][2];
#pragma unroll
        for (int nt = 0; nt < NT; nt++) {
            int c = nCol + nt * 8 + g;
            b[nt][0] = Bs[(k0 + tg) * LDB + c];
            b[nt][1] = Bs[(k0 + tg + 4) * LDB + c];
        }
#pragma unroll
        for (int mt = 0; mt < 2; mt++)
#pragma unroll
            for (int nt = 0; nt < NT; nt++) mma1688(acc[mt][nt], a[mt], b[nt]);
    }

#pragma unroll
    for (int mt = 0; mt < 2; mt++) {
        int r0 = rowBase + mRow + mt * 16 + g;
        int r1 = r0 + 8;
#pragma unroll
        for (int nt = 0; nt < NT; nt++) {
            int c = nCol + nt * 8 + 2 * tg;
            if (r0 < NN)
                *(float2*)&g_bufB[r0 * M + c] = make_float2(acc[mt][nt][0], acc[mt][nt][1]);
            if (r1 < NN)
                *(float2*)&g_bufB[r1 * M + c] = make_float2(acc[mt][nt][2], acc[mt][nt][3]);
        }
    }
}

// ---------------- launcher ----------------------------------------------------
extern "C" void kernel_launch(void* const* d_in, const int* in_sizes, int n_in,
                              void* d_out, int out_size) {
    const float* x  = (const float*)d_in[0];
    const int*   ei = (const int*)d_in[1];
    const float* W1 = (const float*)d_in[2];
    const float* b1 = (const float*)d_in[3];
    const float* W2 = (const float*)d_in[4];
    const float* b2 = (const float*)d_in[5];
    const float* W3 = (const float*)d_in[6];
    const float* b3 = (const float*)d_in[7];
    const float* W4 = (const float*)d_in[8];
    const float* b4 = (const float*)d_in[9];
    const float* W5 = (const float*)d_in[10];
    const float* b5 = (const float*)d_in[11];
    float* out = (float*)d_out;

    constexpr int SM2 = (128 * 132 + 128 * 132) * 4;  // 135168
    constexpr int SM3 = (128 * 132 + 128 * 68) * 4;   // 102400
    constexpr int SM4 = (128 * 68 + 64 * 68) * 4;     // 52224
    cudaFuncSetAttribute(k_tcgemm<128, 128, false>,
                         cudaFuncAttributeMaxDynamicSharedMemorySize, SM2);
    cudaFuncSetAttribute(k_tcgemm<128, 64, true>,
                         cudaFuncAttributeMaxDynamicSharedMemorySize, SM3);
    cudaFuncSetAttribute(k_tcgemm<64, 64, true>,
                         cudaFuncAttributeMaxDynamicSharedMemorySize, SM4);

    const int NB_N = (NN + 255) / 256;
    const int NB_E = (EE + 255) / 256;
    const int NB_W = (NN + 7) / 8;
    const int GB   = (NN + 127) / 128;

    // graph preprocessing: CSR by target + symmetric norms
    k_hist<<<NB_E, 256>>>(ei);
    k_scan<<<98, 1024>>>();
    k_fill<<<NB_E, 256>>>(ei);

    // L1: A1 = Agg(x); H1 = relu(A1 @ W1 + b1)
    k_agg0<<<NB_N, 256>>>(x);
    k_gemm1<<<(NN * 32 + 255) / 256, 256>>>(W1, b1);

    // L2: T2 = H1 @ W2 ; A2 = Agg(T2)
    k_tcgemm<128, 128, false><<<GB, 256, SM2>>>(W2, nullptr);
    k_agg128<<<NB_W, 256>>>();

    // L3: T3 = relu(A2 + b2) @ W3 ; A3 = Agg(T3)
    k_tcgemm<128, 64, true><<<GB, 256, SM3>>>(W3, b2);
    k_agg64<<<NB_W, 256>>>();

    // L4: T4 = relu(A3 + b3) @ W4 ; A4 = Agg(T4)
    k_tcgemm<64, 64, true><<<GB, 256, SM4>>>(W4, b3);
    k_agg64<<<NB_W, 256>>>();

    // L5: s = relu(A4 + b4) @ W5 ; out = Agg(s) + b5
    k_gemm5<<<NB_N, 256>>>(W5, b4);
    k_agg_out<<<NB_N, 256>>>(out, b5);
}